// round 16
// baseline (speedup 1.0000x reference)
#include <cuda_runtime.h>
#include <cuda_bf16.h>
#include <cuda_fp16.h>
#include <cstdint>

// Problem constants (fixed by the dataset)
#define IN_F   128
#define OUT_F  64
#define N_DIV  4
#define N_MAX  100000
#define E_MAX  1600000
#define NSEG_MAX (N_MAX * N_DIV)
#define NBLK_MAX 512

// Scratch: t[d][n][o] = norm[n] * (feature[n] . W[d][o]),  [4, N, 64] fp16 = 51.2 MB
__device__ __half t_buf[(size_t)N_DIV * N_MAX * OUT_F];
// CSR over segments seg = div*N + dst
__device__ int seg_count[NSEG_MAX];
__device__ int seg_start[NSEG_MAX + 1];
__device__ int seg_cursor[NSEG_MAX];
__device__ int sorted_row[E_MAX];   // src node id per edge (div implied by segment)
__device__ int blk_sum[NBLK_MAX];
// fp16 weights (hi only — the 2-pass split drops the w-residual term)
__device__ __half w_half[N_DIV * OUT_F * IN_F];

// ---------------------------------------------------------------------------
// PTX helpers (sm_80-baseline features only: cp.async, ldmatrix, mma.sync)
// ---------------------------------------------------------------------------
__device__ __forceinline__ uint32_t smem_u32(const void* p) {
    uint32_t a;
    asm("{ .reg .u64 t; cvta.to.shared.u64 t, %1; cvt.u32.u64 %0, t; }" : "=r"(a) : "l"(p));
    return a;
}
__device__ __forceinline__ void cp16(uint32_t dst, const void* src, int valid) {
    int sz = valid ? 16 : 0;
    asm volatile("cp.async.cg.shared.global [%0], [%1], 16, %2;"
                 :: "r"(dst), "l"(src), "r"(sz));
}
#define CP_COMMIT() asm volatile("cp.async.commit_group;" ::: "memory")
#define CP_WAIT(n)  asm volatile("cp.async.wait_group %0;" :: "n"(n) : "memory")

__device__ __forceinline__ void ldsm_x4(uint32_t& r0, uint32_t& r1,
                                        uint32_t& r2, uint32_t& r3, uint32_t addr) {
    asm volatile("ldmatrix.sync.aligned.m8n8.x4.shared.b16 {%0,%1,%2,%3}, [%4];"
                 : "=r"(r0), "=r"(r1), "=r"(r2), "=r"(r3) : "r"(addr));
}
__device__ __forceinline__ void mma_f16(float* c, const uint32_t* a,
                                        uint32_t b0, uint32_t b1) {
    asm volatile("mma.sync.aligned.m16n8k16.row.col.f32.f16.f16.f32 "
                 "{%0,%1,%2,%3}, {%4,%5,%6,%7}, {%8,%9}, {%0,%1,%2,%3};"
                 : "+f"(c[0]), "+f"(c[1]), "+f"(c[2]), "+f"(c[3])
                 : "r"(a[0]), "r"(a[1]), "r"(a[2]), "r"(a[3]), "r"(b0), "r"(b1));
}
__device__ __forceinline__ uint32_t sw(uint32_t off) {
    return off ^ ((off >> 3) & 0x70);
}
__device__ __forceinline__ uint32_t pack_h2(__half a, __half b) {
    __half2 t(a, b);
    return *(uint32_t*)&t;
}
__device__ __forceinline__ void acc_q(float* acc, const uint4& q) {
    float2 f0 = __half22float2(*(__half2*)&q.x);
    float2 f1 = __half22float2(*(__half2*)&q.y);
    float2 f2 = __half22float2(*(__half2*)&q.z);
    float2 f3 = __half22float2(*(__half2*)&q.w);
    acc[0] += f0.x; acc[1] += f0.y; acc[2] += f1.x; acc[3] += f1.y;
    acc[4] += f2.x; acc[5] += f2.y; acc[6] += f3.x; acc[7] += f3.y;
}

// ---------------------------------------------------------------------------
// W conversion: f32 -> fp16 (hi only), [4,64,128]
// ---------------------------------------------------------------------------
__global__ void convert_w(const float* __restrict__ x, int count4)
{
    int i = blockIdx.x * blockDim.x + threadIdx.x;
    if (i >= count4) return;
    float4 v = ((const float4*)x)[i];
    __half2* p = (__half2*)&w_half[(size_t)i * 4];
    p[0] = __floats2half2_rn(v.x, v.y);
    p[1] = __floats2half2_rn(v.z, v.w);
}

// ---------------------------------------------------------------------------
// mma.sync fp16 2-pass split GEMM, A-resident all-divisions, fused convert
// (proven free in R14/R15 comparison). Block: 128 nodes x ALL 4 divisions x
// 64 outs, 512 threads. SMEM 96KB; __launch_bounds__(512, 2) targets 2
// CTAs/SM (192KB of the 228KB carveout) so one CTA's load/epilogue phases
// hide under the other's MMA stream.
// ---------------------------------------------------------------------------
__global__ void __launch_bounds__(512, 2) gemm_mma_kernel(
    const float* __restrict__ feat, const float* __restrict__ norm, int N)
{
    extern __shared__ __align__(16) char smem[];
    const uint32_t as_u = smem_u32(smem);          // A: 4 * 16384 = 64KB
    const uint32_t bs_u = as_u + 65536;            // B: 2 * 16384 = 32KB

    const int tid  = threadIdx.x;
    const int lane = tid & 31;
    const int wid  = tid >> 5;
    const int n0   = blockIdx.x * 128;
    const int warp_m = (wid >> 1) * 16;
    const int warp_n = (wid & 1) * 32;

    // ---- B loader: division d -> buffer buf (cp.async), wh only ----
    auto loadB = [&](int buf, int d) {
        uint32_t base = bs_u + buf * 16384;
        #pragma unroll
        for (int it = 0; it < 2; ++it) {
            int id = tid + it * 512;
            int ch = id >> 9, rem = id & 511;
            int m = rem >> 3, u = rem & 7;
            const __half* src = w_half + ((size_t)(d * 64 + m)) * 128 + ch * 64 + u * 8;
            cp16(base + ch * 8192 + sw(m * 128 + u * 16), src, 1);
        }
    };
    loadB(0, 0);
    CP_COMMIT();

    // ---- fused A load+convert: f32 feature -> fp16 hi/lo split in smem ----
    const float4* fsrc = (const float4*)feat;
    #pragma unroll
    for (int it = 0; it < 4; ++it) {
        int id = tid + it * 512;
        int m = id >> 4, g = id & 15;
        int n = n0 + m;
        float4 v0 = make_float4(0.f, 0.f, 0.f, 0.f), v1 = v0;
        if (n < N) {
            v0 = fsrc[(size_t)n * 32 + g * 2];
            v1 = fsrc[(size_t)n * 32 + g * 2 + 1];
        }
        float f[8] = { v0.x, v0.y, v0.z, v0.w, v1.x, v1.y, v1.z, v1.w };
        __half h[8], l[8];
        #pragma unroll
        for (int q = 0; q < 8; ++q) {
            h[q] = __float2half_rn(f[q]);
            l[q] = __float2half_rn(f[q] - __half2float(h[q]));
        }
        uint4 hv = make_uint4(pack_h2(h[0], h[1]), pack_h2(h[2], h[3]),
                              pack_h2(h[4], h[5]), pack_h2(h[6], h[7]));
        uint4 lv = make_uint4(pack_h2(l[0], l[1]), pack_h2(l[2], l[3]),
                              pack_h2(l[4], l[5]), pack_h2(l[6], l[7]));
        int ch = g >> 3, u = g & 7;
        uint32_t off = sw(m * 128 + u * 16);
        *(uint4*)(smem + ch * 16384 + off)       = hv;   // xh chunk 0/1
        *(uint4*)(smem + (2 + ch) * 16384 + off) = lv;   // xl chunk 0/1
    }

    // pass tables: xh0·wh0, xh1·wh1, xl0·wh0, xl1·wh1
    const int ac[4] = { 0, 1, 2, 3 };
    const int bc[4] = { 0, 1, 0, 1 };

    float acc[4][4];
    #pragma unroll
    for (int j = 0; j < 4; ++j)
        #pragma unroll
        for (int k = 0; k < 4; ++k) acc[j][k] = 0.f;

    int buf = 0;
    for (int d = 0; d < N_DIV; ++d) {
        if (d < N_DIV - 1) {
            loadB(buf ^ 1, d + 1);
            CP_COMMIT();
            CP_WAIT(1);
        } else {
            CP_WAIT(0);
        }
        __syncthreads();                    // B[d] + A (regular stores) ready

        const uint32_t bbase0 = bs_u + buf * 16384;
        #pragma unroll
        for (int c = 0; c < 4; ++c) {
            const uint32_t abase = as_u + ac[c] * 16384;
            const uint32_t bbase = bbase0 + bc[c] * 8192;
            #pragma unroll
            for (int k16 = 0; k16 < 4; ++k16) {
                uint32_t a[4], b[2][4];
                {
                    int m = warp_m + (lane & 15);
                    int u = k16 * 2 + (lane >> 4);
                    ldsm_x4(a[0], a[1], a[2], a[3], abase + sw(m * 128 + u * 16));
                }
                #pragma unroll
                for (int ni = 0; ni < 2; ++ni) {
                    int n = warp_n + ni * 16 + (lane & 7) + ((lane >> 4) << 3);
                    int u = k16 * 2 + ((lane >> 3) & 1);
                    ldsm_x4(b[ni][0], b[ni][1], b[ni][2], b[ni][3],
                            bbase + sw(n * 128 + u * 16));
                }
                #pragma unroll
                for (int j = 0; j < 4; ++j) {
                    int ni = j >> 1, h = j & 1;
                    mma_f16(acc[j], a, b[ni][h * 2], b[ni][h * 2 + 1]);
                }
            }
        }
        __syncthreads();                    // all reads of buf done before reuse

        // ---- epilogue for division d: norm scale, fp16 store, clear acc ----
        {
            int r0 = n0 + warp_m + (lane >> 2);
            int r1 = r0 + 8;
            float nm0 = (r0 < N) ? norm[r0] : 0.f;
            float nm1 = (r1 < N) ? norm[r1] : 0.f;
            #pragma unroll
            for (int j = 0; j < 4; ++j) {
                int col = warp_n + j * 8 + (lane & 3) * 2;
                if (r0 < N) {
                    __half2 v = __floats2half2_rn(acc[j][0] * nm0, acc[j][1] * nm0);
                    *(__half2*)&t_buf[((size_t)d * N + r0) * OUT_F + col] = v;
                }
                if (r1 < N) {
                    __half2 v = __floats2half2_rn(acc[j][2] * nm1, acc[j][3] * nm1);
                    *(__half2*)&t_buf[((size_t)d * N + r1) * OUT_F + col] = v;
                }
                acc[j][0] = acc[j][1] = acc[j][2] = acc[j][3] = 0.f;
            }
        }
        buf ^= 1;
    }
}

// ---------------------------------------------------------------------------
// CSR build (div-major segments: seg = div*N + dst)
// ---------------------------------------------------------------------------
__global__ void zero_counts_kernel(int nseg)
{
    int i = blockIdx.x * blockDim.x + threadIdx.x;
    if (i < nseg) seg_count[i] = 0;
}

__global__ void hist_kernel(const int* __restrict__ dst,
                            const int* __restrict__ ediv, int E, int N)
{
    int e = blockIdx.x * blockDim.x + threadIdx.x;
    if (e >= E) return;
    int seg = ediv[e] * N + dst[e];
    atomicAdd(&seg_count[seg], 1);
}

__global__ void __launch_bounds__(1024) scan_block_sum(int nseg)
{
    __shared__ int wsum[32];
    int i = blockIdx.x * 1024 + threadIdx.x;
    int lane = threadIdx.x & 31;
    int wid  = threadIdx.x >> 5;
    int x = (i < nseg) ? seg_count[i] : 0;
    #pragma unroll
    for (int o = 16; o; o >>= 1) x += __shfl_down_sync(0xffffffffu, x, o);
    if (lane == 0) wsum[wid] = x;
    __syncthreads();
    if (wid == 0) {
        int y = wsum[lane];
        #pragma unroll
        for (int o = 16; o; o >>= 1) y += __shfl_down_sync(0xffffffffu, y, o);
        if (lane == 0) blk_sum[blockIdx.x] = y;
    }
}

__global__ void __launch_bounds__(512) scan_partials(int nblk, int nseg)
{
    __shared__ int sh[512];
    int tid = threadIdx.x;
    int v = (tid < nblk) ? blk_sum[tid] : 0;
    sh[tid] = v;
    __syncthreads();
    #pragma unroll
    for (int off = 1; off < 512; off <<= 1) {
        int u = (tid >= off) ? sh[tid - off] : 0;
        __syncthreads();
        sh[tid] += u;
        __syncthreads();
    }
    if (tid < nblk) blk_sum[tid] = sh[tid] - v;
    if (tid == nblk - 1) seg_start[nseg] = sh[tid];
}

__global__ void __launch_bounds__(1024) scan_final(int nseg)
{
    __shared__ int wsum[32];
    __shared__ int wbase[32];
    int i = blockIdx.x * 1024 + threadIdx.x;
    int lane = threadIdx.x & 31;
    int wid  = threadIdx.x >> 5;
    int v = (i < nseg) ? seg_count[i] : 0;
    int x = v;
    #pragma unroll
    for (int o = 1; o < 32; o <<= 1) {
        int u = __shfl_up_sync(0xffffffffu, x, o);
        if (lane >= o) x += u;
    }
    if (lane == 31) wsum[wid] = x;
    __syncthreads();
    if (wid == 0) {
        int y = wsum[lane];
        int z = y;
        #pragma unroll
        for (int o = 1; o < 32; o <<= 1) {
            int u = __shfl_up_sync(0xffffffffu, z, o);
            if (lane >= o) z += u;
        }
        wbase[lane] = z - y;
    }
    __syncthreads();
    if (i < nseg) {
        int off = blk_sum[blockIdx.x] + wbase[wid] + (x - v);
        seg_start[i]  = off;
        seg_cursor[i] = off;
    }
}

__global__ void fill_kernel(const int* __restrict__ src,
                            const int* __restrict__ dst,
                            const int* __restrict__ ediv, int E, int N)
{
    int e = blockIdx.x * blockDim.x + threadIdx.x;
    if (e >= E) return;
    int seg = ediv[e] * N + dst[e];
    int pos = atomicAdd(&seg_cursor[seg], 1);
    sorted_row[pos] = src[e];
}

// ---------------------------------------------------------------------------
// Gather-accumulate over fp16 t_buf: 8 threads per segment, each owns one
// uint4 (16B = 8 halves) of the 128B row. Unroll-4 for MLP=4.
// fp32 accumulation, fused norm*relu output (two float4 stores per thread).
// ---------------------------------------------------------------------------
__global__ void __launch_bounds__(256) gather_kernel(
    const float* __restrict__ norm,
    float* __restrict__ out, int nseg, int N)
{
    int g = blockIdx.x * 32 + (threadIdx.x >> 3);
    if (g >= nseg) return;
    int lane = threadIdx.x & 7;

    int dv  = g / N;            // division
    int dn  = g - dv * N;       // dst node

    int b  = seg_start[g];
    int e2 = seg_start[g + 1];

    const uint4* tb = (const uint4*)t_buf + (size_t)dv * N * 8;
    float acc[8] = { 0.f, 0.f, 0.f, 0.f, 0.f, 0.f, 0.f, 0.f };

    int i = b;
    for (; i + 4 <= e2; i += 4) {
        int r0 = sorted_row[i];
        int r1 = sorted_row[i + 1];
        int r2 = sorted_row[i + 2];
        int r3 = sorted_row[i + 3];
        uint4 q0 = __ldg(&tb[(size_t)r0 * 8 + lane]);
        uint4 q1 = __ldg(&tb[(size_t)r1 * 8 + lane]);
        uint4 q2 = __ldg(&tb[(size_t)r2 * 8 + lane]);
        uint4 q3 = __ldg(&tb[(size_t)r3 * 8 + lane]);
        acc_q(acc, q0); acc_q(acc, q1); acc_q(acc, q2); acc_q(acc, q3);
    }
    for (; i < e2; ++i) {
        int r0 = sorted_row[i];
        uint4 q0 = __ldg(&tb[(size_t)r0 * 8 + lane]);
        acc_q(acc, q0);
    }

    float nm = norm[dn];
    float4 o0, o1;
    o0.x = fmaxf(acc[0] * nm, 0.f);
    o0.y = fmaxf(acc[1] * nm, 0.f);
    o0.z = fmaxf(acc[2] * nm, 0.f);
    o0.w = fmaxf(acc[3] * nm, 0.f);
    o1.x = fmaxf(acc[4] * nm, 0.f);
    o1.y = fmaxf(acc[5] * nm, 0.f);
    o1.z = fmaxf(acc[6] * nm, 0.f);
    o1.w = fmaxf(acc[7] * nm, 0.f);
    float4* op = (float4*)out + (size_t)dn * 64 + dv * 16 + lane * 2;
    op[0] = o0;
    op[1] = o1;
}

// ---------------------------------------------------------------------------
extern "C" void kernel_launch(void* const* d_in, const int* in_sizes, int n_in,
                              void* d_out, int out_size)
{
    const float* feat = (const float*)d_in[0];
    const float* W    = (const float*)d_in[1];
    const float* norm = (const float*)d_in[2];
    const int*   src  = (const int*)d_in[3];
    const int*   dst  = (const int*)d_in[4];
    const int*   ediv = (const int*)d_in[5];
    float*       out  = (float*)d_out;

    const int N    = in_sizes[2];            // 100000
    const int E    = in_sizes[3];            // 1600000
    const int nseg = N * N_DIV;              // 400000
    const int nblk = (nseg + 1023) / 1024;   // 391

    // one-time infra (created on the correctness call, outside graph capture)
    static cudaStream_t s2 = nullptr;
    static cudaEvent_t ev_fork = nullptr, ev_join = nullptr;
    if (!s2) {
        cudaStreamCreateWithFlags(&s2, cudaStreamNonBlocking);
        cudaEventCreateWithFlags(&ev_fork, cudaEventDisableTiming);
        cudaEventCreateWithFlags(&ev_join, cudaEventDisableTiming);
        cudaFuncSetAttribute(gemm_mma_kernel,
                             cudaFuncAttributeMaxDynamicSharedMemorySize, 98304);
    }

    // ---- fork: CSR build on s2 (kernel launches only), concurrent with
    //      convert_w + GEMM on stream 0 ----
    cudaEventRecord(ev_fork, 0);
    cudaStreamWaitEvent(s2, ev_fork, 0);

    zero_counts_kernel<<<(nseg + 255) / 256, 256, 0, s2>>>(nseg);
    hist_kernel<<<(E + 255) / 256, 256, 0, s2>>>(dst, ediv, E, N);
    scan_block_sum<<<nblk, 1024, 0, s2>>>(nseg);
    scan_partials<<<1, 512, 0, s2>>>(nblk, nseg);
    scan_final<<<nblk, 1024, 0, s2>>>(nseg);
    fill_kernel<<<(E + 255) / 256, 256, 0, s2>>>(src, dst, ediv, E, N);
    cudaEventRecord(ev_join, s2);

    // ---- stream 0: W convert -> GEMM (fused feature convert inside) ----
    int wc4 = (N_DIV * OUT_F * IN_F) / 4;
    convert_w<<<(wc4 + 255) / 256, 256>>>(W, wc4);

    gemm_mma_kernel<<<(N + 127) / 128, 512, 98304>>>(feat, norm, N);

    // ---- join: gather needs both t_buf (stream 0) and CSR (s2) ----
    cudaStreamWaitEvent(0, ev_join, 0);
    gather_kernel<<<(nseg + 31) / 32, 256>>>(norm, out, nseg, N);
}

// round 17
// speedup vs baseline: 1.3392x; 1.3392x over previous
#include <cuda_runtime.h>
#include <cuda_bf16.h>
#include <cuda_fp16.h>
#include <cstdint>

// Problem constants (fixed by the dataset)
#define IN_F   128
#define OUT_F  64
#define N_DIV  4
#define N_MAX  100000
#define E_MAX  1600000
#define NSEG_MAX (N_MAX * N_DIV)
#define NBLK_MAX 512

// Scratch: t[d][n][o] = norm[n] * (feature[n] . W[d][o]),  [4, N, 64] fp16 = 51.2 MB
__device__ __half t_buf[(size_t)N_DIV * N_MAX * OUT_F];
// CSR over segments seg = div*N + dst
__device__ int seg_count[NSEG_MAX];
__device__ int seg_start[NSEG_MAX + 1];
__device__ int seg_cursor[NSEG_MAX];
__device__ int sorted_row[E_MAX];   // src node id per edge (div implied by segment)
__device__ int blk_sum[NBLK_MAX];
// fp16 weights (hi only — the 2-pass split drops the w-residual term)
__device__ __half w_half[N_DIV * OUT_F * IN_F];

// ---------------------------------------------------------------------------
// PTX helpers (sm_80-baseline features only: cp.async, ldmatrix, mma.sync)
// ---------------------------------------------------------------------------
__device__ __forceinline__ uint32_t smem_u32(const void* p) {
    uint32_t a;
    asm("{ .reg .u64 t; cvta.to.shared.u64 t, %1; cvt.u32.u64 %0, t; }" : "=r"(a) : "l"(p));
    return a;
}
__device__ __forceinline__ void cp16(uint32_t dst, const void* src, int valid) {
    int sz = valid ? 16 : 0;
    asm volatile("cp.async.cg.shared.global [%0], [%1], 16, %2;"
                 :: "r"(dst), "l"(src), "r"(sz));
}
#define CP_COMMIT() asm volatile("cp.async.commit_group;" ::: "memory")
#define CP_WAIT(n)  asm volatile("cp.async.wait_group %0;" :: "n"(n) : "memory")

__device__ __forceinline__ void ldsm_x4(uint32_t& r0, uint32_t& r1,
                                        uint32_t& r2, uint32_t& r3, uint32_t addr) {
    asm volatile("ldmatrix.sync.aligned.m8n8.x4.shared.b16 {%0,%1,%2,%3}, [%4];"
                 : "=r"(r0), "=r"(r1), "=r"(r2), "=r"(r3) : "r"(addr));
}
__device__ __forceinline__ void mma_f16(float* c, const uint32_t* a,
                                        uint32_t b0, uint32_t b1) {
    asm volatile("mma.sync.aligned.m16n8k16.row.col.f32.f16.f16.f32 "
                 "{%0,%1,%2,%3}, {%4,%5,%6,%7}, {%8,%9}, {%0,%1,%2,%3};"
                 : "+f"(c[0]), "+f"(c[1]), "+f"(c[2]), "+f"(c[3])
                 : "r"(a[0]), "r"(a[1]), "r"(a[2]), "r"(a[3]), "r"(b0), "r"(b1));
}
__device__ __forceinline__ uint32_t sw(uint32_t off) {
    return off ^ ((off >> 3) & 0x70);
}
__device__ __forceinline__ uint32_t pack_h2(__half a, __half b) {
    __half2 t(a, b);
    return *(uint32_t*)&t;
}
__device__ __forceinline__ void acc_q(float* acc, const uint4& q) {
    float2 f0 = __half22float2(*(__half2*)&q.x);
    float2 f1 = __half22float2(*(__half2*)&q.y);
    float2 f2 = __half22float2(*(__half2*)&q.z);
    float2 f3 = __half22float2(*(__half2*)&q.w);
    acc[0] += f0.x; acc[1] += f0.y; acc[2] += f1.x; acc[3] += f1.y;
    acc[4] += f2.x; acc[5] += f2.y; acc[6] += f3.x; acc[7] += f3.y;
}

// ---------------------------------------------------------------------------
// W conversion: f32 -> fp16 (hi only), [4,64,128]
// ---------------------------------------------------------------------------
__global__ void convert_w(const float* __restrict__ x, int count4)
{
    int i = blockIdx.x * blockDim.x + threadIdx.x;
    if (i >= count4) return;
    float4 v = ((const float4*)x)[i];
    __half2* p = (__half2*)&w_half[(size_t)i * 4];
    p[0] = __floats2half2_rn(v.x, v.y);
    p[1] = __floats2half2_rn(v.z, v.w);
}

// ---------------------------------------------------------------------------
// mma.sync fp16 2-pass split GEMM, 64-row tile, all divisions, fused convert.
// Block: 64 nodes x 4 divisions x 64 outs, 256 threads (8 warps).
// SMEM 64KB: A = 4 chunks x 8KB (xh0,xh1,xl0,xl1) built in-kernel from f32;
// B = 2 x 16KB (wh) double-buffered across divisions.
// 64KB smem + ~90 regs @256 thr -> 2 CTAs/SM co-resident with NO reg cap:
// one CTA's load/convert/epilogue phases hide under the other's MMA stream.
// ---------------------------------------------------------------------------
__global__ void __launch_bounds__(256) gemm_mma_kernel(
    const float* __restrict__ feat, const float* __restrict__ norm, int N)
{
    extern __shared__ __align__(16) char smem[];
    const uint32_t as_u = smem_u32(smem);          // A: 4 * 8192 = 32KB
    const uint32_t bs_u = as_u + 32768;            // B: 2 * 16384 = 32KB

    const int tid  = threadIdx.x;
    const int lane = tid & 31;
    const int wid  = tid >> 5;
    const int n0   = blockIdx.x * 64;
    const int warp_m = (wid >> 1) * 16;            // 4 m-groups of 16 rows
    const int warp_n = (wid & 1) * 32;             // 2 n-groups of 32 cols

    // ---- B loader: division d -> buffer buf (cp.async), wh only ----
    auto loadB = [&](int buf, int d) {
        uint32_t base = bs_u + buf * 16384;
        #pragma unroll
        for (int it = 0; it < 4; ++it) {           // 1024 16B units
            int id = tid + it * 256;
            int ch = id >> 9, rem = id & 511;
            int m = rem >> 3, u = rem & 7;
            const __half* src = w_half + ((size_t)(d * 64 + m)) * 128 + ch * 64 + u * 8;
            cp16(base + ch * 8192 + sw(m * 128 + u * 16), src, 1);
        }
    };
    loadB(0, 0);
    CP_COMMIT();

    // ---- fused A load+convert: f32 feature -> fp16 hi/lo split in smem ----
    const float4* fsrc = (const float4*)feat;
    #pragma unroll
    for (int it = 0; it < 4; ++it) {
        int id = tid + it * 256;                   // 1024 groups of 8 k-values
        int m = id >> 4, g = id & 15;
        int n = n0 + m;
        float4 v0 = make_float4(0.f, 0.f, 0.f, 0.f), v1 = v0;
        if (n < N) {
            v0 = fsrc[(size_t)n * 32 + g * 2];
            v1 = fsrc[(size_t)n * 32 + g * 2 + 1];
        }
        float f[8] = { v0.x, v0.y, v0.z, v0.w, v1.x, v1.y, v1.z, v1.w };
        __half h[8], l[8];
        #pragma unroll
        for (int q = 0; q < 8; ++q) {
            h[q] = __float2half_rn(f[q]);
            l[q] = __float2half_rn(f[q] - __half2float(h[q]));
        }
        uint4 hv = make_uint4(pack_h2(h[0], h[1]), pack_h2(h[2], h[3]),
                              pack_h2(h[4], h[5]), pack_h2(h[6], h[7]));
        uint4 lv = make_uint4(pack_h2(l[0], l[1]), pack_h2(l[2], l[3]),
                              pack_h2(l[4], l[5]), pack_h2(l[6], l[7]));
        int ch = g >> 3, u = g & 7;
        uint32_t off = sw(m * 128 + u * 16);
        *(uint4*)(smem + ch * 8192 + off)       = hv;    // xh chunk 0/1
        *(uint4*)(smem + (2 + ch) * 8192 + off) = lv;    // xl chunk 0/1
    }

    // pass tables: xh0·wh0, xh1·wh1, xl0·wh0, xl1·wh1
    const int ac[4] = { 0, 1, 2, 3 };
    const int bc[4] = { 0, 1, 0, 1 };

    float acc[4][4];
    #pragma unroll
    for (int j = 0; j < 4; ++j)
        #pragma unroll
        for (int k = 0; k < 4; ++k) acc[j][k] = 0.f;

    int buf = 0;
    for (int d = 0; d < N_DIV; ++d) {
        if (d < N_DIV - 1) {
            loadB(buf ^ 1, d + 1);
            CP_COMMIT();
            CP_WAIT(1);
        } else {
            CP_WAIT(0);
        }
        __syncthreads();                    // B[d] + A (regular stores) ready

        const uint32_t bbase0 = bs_u + buf * 16384;
        #pragma unroll
        for (int c = 0; c < 4; ++c) {
            const uint32_t abase = as_u + ac[c] * 8192;
            const uint32_t bbase = bbase0 + bc[c] * 8192;
            #pragma unroll
            for (int k16 = 0; k16 < 4; ++k16) {
                uint32_t a[4], b[2][4];
                {
                    int m = warp_m + (lane & 15);
                    int u = k16 * 2 + (lane >> 4);
                    ldsm_x4(a[0], a[1], a[2], a[3], abase + sw(m * 128 + u * 16));
                }
                #pragma unroll
                for (int ni = 0; ni < 2; ++ni) {
                    int n = warp_n + ni * 16 + (lane & 7) + ((lane >> 4) << 3);
                    int u = k16 * 2 + ((lane >> 3) & 1);
                    ldsm_x4(b[ni][0], b[ni][1], b[ni][2], b[ni][3],
                            bbase + sw(n * 128 + u * 16));
                }
                #pragma unroll
                for (int j = 0; j < 4; ++j) {
                    int ni = j >> 1, h = j & 1;
                    mma_f16(acc[j], a, b[ni][h * 2], b[ni][h * 2 + 1]);
                }
            }
        }
        __syncthreads();                    // all reads of buf done before reuse

        // ---- epilogue for division d: norm scale, fp16 store, clear acc ----
        {
            int r0 = n0 + warp_m + (lane >> 2);
            int r1 = r0 + 8;
            float nm0 = (r0 < N) ? norm[r0] : 0.f;
            float nm1 = (r1 < N) ? norm[r1] : 0.f;
            #pragma unroll
            for (int j = 0; j < 4; ++j) {
                int col = warp_n + j * 8 + (lane & 3) * 2;
                if (r0 < N) {
                    __half2 v = __floats2half2_rn(acc[j][0] * nm0, acc[j][1] * nm0);
                    *(__half2*)&t_buf[((size_t)d * N + r0) * OUT_F + col] = v;
                }
                if (r1 < N) {
                    __half2 v = __floats2half2_rn(acc[j][2] * nm1, acc[j][3] * nm1);
                    *(__half2*)&t_buf[((size_t)d * N + r1) * OUT_F + col] = v;
                }
                acc[j][0] = acc[j][1] = acc[j][2] = acc[j][3] = 0.f;
            }
        }
        buf ^= 1;
    }
}

// ---------------------------------------------------------------------------
// CSR build (div-major segments: seg = div*N + dst)
// ---------------------------------------------------------------------------
__global__ void zero_counts_kernel(int nseg)
{
    int i = blockIdx.x * blockDim.x + threadIdx.x;
    if (i < nseg) seg_count[i] = 0;
}

__global__ void hist_kernel(const int* __restrict__ dst,
                            const int* __restrict__ ediv, int E, int N)
{
    int e = blockIdx.x * blockDim.x + threadIdx.x;
    if (e >= E) return;
    int seg = ediv[e] * N + dst[e];
    atomicAdd(&seg_count[seg], 1);
}

__global__ void __launch_bounds__(1024) scan_block_sum(int nseg)
{
    __shared__ int wsum[32];
    int i = blockIdx.x * 1024 + threadIdx.x;
    int lane = threadIdx.x & 31;
    int wid  = threadIdx.x >> 5;
    int x = (i < nseg) ? seg_count[i] : 0;
    #pragma unroll
    for (int o = 16; o; o >>= 1) x += __shfl_down_sync(0xffffffffu, x, o);
    if (lane == 0) wsum[wid] = x;
    __syncthreads();
    if (wid == 0) {
        int y = wsum[lane];
        #pragma unroll
        for (int o = 16; o; o >>= 1) y += __shfl_down_sync(0xffffffffu, y, o);
        if (lane == 0) blk_sum[blockIdx.x] = y;
    }
}

__global__ void __launch_bounds__(512) scan_partials(int nblk, int nseg)
{
    __shared__ int sh[512];
    int tid = threadIdx.x;
    int v = (tid < nblk) ? blk_sum[tid] : 0;
    sh[tid] = v;
    __syncthreads();
    #pragma unroll
    for (int off = 1; off < 512; off <<= 1) {
        int u = (tid >= off) ? sh[tid - off] : 0;
        __syncthreads();
        sh[tid] += u;
        __syncthreads();
    }
    if (tid < nblk) blk_sum[tid] = sh[tid] - v;
    if (tid == nblk - 1) seg_start[nseg] = sh[tid];
}

__global__ void __launch_bounds__(1024) scan_final(int nseg)
{
    __shared__ int wsum[32];
    __shared__ int wbase[32];
    int i = blockIdx.x * 1024 + threadIdx.x;
    int lane = threadIdx.x & 31;
    int wid  = threadIdx.x >> 5;
    int v = (i < nseg) ? seg_count[i] : 0;
    int x = v;
    #pragma unroll
    for (int o = 1; o < 32; o <<= 1) {
        int u = __shfl_up_sync(0xffffffffu, x, o);
        if (lane >= o) x += u;
    }
    if (lane == 31) wsum[wid] = x;
    __syncthreads();
    if (wid == 0) {
        int y = wsum[lane];
        int z = y;
        #pragma unroll
        for (int o = 1; o < 32; o <<= 1) {
            int u = __shfl_up_sync(0xffffffffu, z, o);
            if (lane >= o) z += u;
        }
        wbase[lane] = z - y;
    }
    __syncthreads();
    if (i < nseg) {
        int off = blk_sum[blockIdx.x] + wbase[wid] + (x - v);
        seg_start[i]  = off;
        seg_cursor[i] = off;
    }
}

__global__ void fill_kernel(const int* __restrict__ src,
                            const int* __restrict__ dst,
                            const int* __restrict__ ediv, int E, int N)
{
    int e = blockIdx.x * blockDim.x + threadIdx.x;
    if (e >= E) return;
    int seg = ediv[e] * N + dst[e];
    int pos = atomicAdd(&seg_cursor[seg], 1);
    sorted_row[pos] = src[e];
}

// ---------------------------------------------------------------------------
// Gather-accumulate over fp16 t_buf: 8 threads per segment, each owns one
// uint4 (16B = 8 halves) of the 128B row. Unroll-4 for MLP=4.
// fp32 accumulation, fused norm*relu output (two float4 stores per thread).
// ---------------------------------------------------------------------------
__global__ void __launch_bounds__(256) gather_kernel(
    const float* __restrict__ norm,
    float* __restrict__ out, int nseg, int N)
{
    int g = blockIdx.x * 32 + (threadIdx.x >> 3);
    if (g >= nseg) return;
    int lane = threadIdx.x & 7;

    int dv  = g / N;            // division
    int dn  = g - dv * N;       // dst node

    int b  = seg_start[g];
    int e2 = seg_start[g + 1];

    const uint4* tb = (const uint4*)t_buf + (size_t)dv * N * 8;
    float acc[8] = { 0.f, 0.f, 0.f, 0.f, 0.f, 0.f, 0.f, 0.f };

    int i = b;
    for (; i + 4 <= e2; i += 4) {
        int r0 = sorted_row[i];
        int r1 = sorted_row[i + 1];
        int r2 = sorted_row[i + 2];
        int r3 = sorted_row[i + 3];
        uint4 q0 = __ldg(&tb[(size_t)r0 * 8 + lane]);
        uint4 q1 = __ldg(&tb[(size_t)r1 * 8 + lane]);
        uint4 q2 = __ldg(&tb[(size_t)r2 * 8 + lane]);
        uint4 q3 = __ldg(&tb[(size_t)r3 * 8 + lane]);
        acc_q(acc, q0); acc_q(acc, q1); acc_q(acc, q2); acc_q(acc, q3);
    }
    for (; i < e2; ++i) {
        int r0 = sorted_row[i];
        uint4 q0 = __ldg(&tb[(size_t)r0 * 8 + lane]);
        acc_q(acc, q0);
    }

    float nm = norm[dn];
    float4 o0, o1;
    o0.x = fmaxf(acc[0] * nm, 0.f);
    o0.y = fmaxf(acc[1] * nm, 0.f);
    o0.z = fmaxf(acc[2] * nm, 0.f);
    o0.w = fmaxf(acc[3] * nm, 0.f);
    o1.x = fmaxf(acc[4] * nm, 0.f);
    o1.y = fmaxf(acc[5] * nm, 0.f);
    o1.z = fmaxf(acc[6] * nm, 0.f);
    o1.w = fmaxf(acc[7] * nm, 0.f);
    float4* op = (float4*)out + (size_t)dn * 64 + dv * 16 + lane * 2;
    op[0] = o0;
    op[1] = o1;
}

// ---------------------------------------------------------------------------
extern "C" void kernel_launch(void* const* d_in, const int* in_sizes, int n_in,
                              void* d_out, int out_size)
{
    const float* feat = (const float*)d_in[0];
    const float* W    = (const float*)d_in[1];
    const float* norm = (const float*)d_in[2];
    const int*   src  = (const int*)d_in[3];
    const int*   dst  = (const int*)d_in[4];
    const int*   ediv = (const int*)d_in[5];
    float*       out  = (float*)d_out;

    const int N    = in_sizes[2];            // 100000
    const int E    = in_sizes[3];            // 1600000
    const int nseg = N * N_DIV;              // 400000
    const int nblk = (nseg + 1023) / 1024;   // 391

    // one-time infra (created on the correctness call, outside graph capture)
    static cudaStream_t s2 = nullptr;
    static cudaEvent_t ev_fork = nullptr, ev_join = nullptr;
    if (!s2) {
        cudaStreamCreateWithFlags(&s2, cudaStreamNonBlocking);
        cudaEventCreateWithFlags(&ev_fork, cudaEventDisableTiming);
        cudaEventCreateWithFlags(&ev_join, cudaEventDisableTiming);
        cudaFuncSetAttribute(gemm_mma_kernel,
                             cudaFuncAttributeMaxDynamicSharedMemorySize, 65536);
    }

    // ---- fork: CSR build on s2 (kernel launches only), concurrent with
    //      convert_w + GEMM on stream 0 ----
    cudaEventRecord(ev_fork, 0);
    cudaStreamWaitEvent(s2, ev_fork, 0);

    zero_counts_kernel<<<(nseg + 255) / 256, 256, 0, s2>>>(nseg);
    hist_kernel<<<(E + 255) / 256, 256, 0, s2>>>(dst, ediv, E, N);
    scan_block_sum<<<nblk, 1024, 0, s2>>>(nseg);
    scan_partials<<<1, 512, 0, s2>>>(nblk, nseg);
    scan_final<<<nblk, 1024, 0, s2>>>(nseg);
    fill_kernel<<<(E + 255) / 256, 256, 0, s2>>>(src, dst, ediv, E, N);
    cudaEventRecord(ev_join, s2);

    // ---- stream 0: W convert -> GEMM (fused feature convert inside) ----
    int wc4 = (N_DIV * OUT_F * IN_F) / 4;
    convert_w<<<(wc4 + 255) / 256, 256>>>(W, wc4);

    gemm_mma_kernel<<<(N + 63) / 64, 256, 65536>>>(feat, norm, N);

    // ---- join: gather needs both t_buf (stream 0) and CSR (s2) ----
    cudaStreamWaitEvent(0, ev_join, 0);
    gather_kernel<<<(nseg + 31) / 32, 256>>>(norm, out, nseg, N);
}